// round 10
// baseline (speedup 1.0000x reference)
#include <cuda_runtime.h>
#include <cuda_bf16.h>
#include <cuda_fp16.h>
#include <cstdint>

// Problem constants
constexpr int NB  = 8;
constexpr int NS  = 1025;
constexpr int ND  = 768;
constexpr int NH  = 12;
constexpr int NHD = 64;
constexpr int NM  = NB * NS;      // 8200

// Scratch
__device__ __half g_qh[(size_t)NB * NH * NS * NHD];   // q * 0.125, fp16
__device__ __half g_kh[(size_t)NB * NH * NS * NHD];
__device__ __half g_vh[(size_t)NB * NH * NS * NHD];
__device__ __half g_ahi[(size_t)NM * ND];             // hidden hi (fp16)
__device__ __half g_alo[(size_t)NM * ND];             // hidden residual (fp16)
__device__ __half g_wt[(size_t)3 * ND * ND];          // W transposed [n][k], fp16

// ---------------------------------------------------------------------------
// PTX helpers
// ---------------------------------------------------------------------------
__device__ __forceinline__ uint32_t smem_to_u32(const void* p) {
    uint32_t a;
    asm("{ .reg .u64 t; cvta.to.shared.u64 t, %1; cvt.u32.u64 %0, t; }"
        : "=r"(a) : "l"(p));
    return a;
}
__device__ __forceinline__ void ldsm_x4(uint32_t& r0, uint32_t& r1,
                                        uint32_t& r2, uint32_t& r3,
                                        uint32_t addr) {
    asm volatile("ldmatrix.sync.aligned.m8n8.x4.shared.b16 {%0,%1,%2,%3}, [%4];"
                 : "=r"(r0), "=r"(r1), "=r"(r2), "=r"(r3) : "r"(addr));
}
__device__ __forceinline__ void ldsm_x4_trans(uint32_t& r0, uint32_t& r1,
                                              uint32_t& r2, uint32_t& r3,
                                              uint32_t addr) {
    asm volatile("ldmatrix.sync.aligned.m8n8.x4.trans.shared.b16 {%0,%1,%2,%3}, [%4];"
                 : "=r"(r0), "=r"(r1), "=r"(r2), "=r"(r3) : "r"(addr));
}
__device__ __forceinline__ void mma_16816_f16(
    float& c0, float& c1, float& c2, float& c3,
    uint32_t a0, uint32_t a1, uint32_t a2, uint32_t a3,
    uint32_t b0, uint32_t b1) {
    asm volatile(
        "mma.sync.aligned.m16n8k16.row.col.f32.f16.f16.f32 "
        "{%0,%1,%2,%3}, {%4,%5,%6,%7}, {%8,%9}, {%0,%1,%2,%3};"
        : "+f"(c0), "+f"(c1), "+f"(c2), "+f"(c3)
        : "r"(a0), "r"(a1), "r"(a2), "r"(a3), "r"(b0), "r"(b1));
}
__device__ __forceinline__ uint32_t pack_h2(float lo, float hi) {
    uint32_t r;
    asm("cvt.rn.f16x2.f32 %0, %1, %2;" : "=r"(r) : "f"(hi), "f"(lo));
    return r;
}
__device__ __forceinline__ void cp_async16(uint32_t dst, const void* src,
                                           int szbytes) {
    asm volatile("cp.async.cg.shared.global [%0], [%1], 16, %2;"
                 :: "r"(dst), "l"(src), "r"(szbytes));
}
#define CP_COMMIT() asm volatile("cp.async.commit_group;" ::: "memory")
#define CP_WAIT(n)  asm volatile("cp.async.wait_group %0;" :: "n"(n) : "memory")

// ---------------------------------------------------------------------------
// Kernel A: split hidden_states fp32 -> (hi, lo) fp16
// ---------------------------------------------------------------------------
__global__ __launch_bounds__(256) void aconv_kernel(const float* __restrict__ A)
{
    size_t i = ((size_t)blockIdx.x * 256 + threadIdx.x) * 4;
    if (i >= (size_t)NM * ND) return;
    float4 v = *(const float4*)(A + i);
    __half h0 = __float2half(v.x), h1 = __float2half(v.y);
    __half h2 = __float2half(v.z), h3 = __float2half(v.w);
    __half l0 = __float2half(v.x - __half2float(h0));
    __half l1 = __float2half(v.y - __half2float(h1));
    __half l2 = __float2half(v.z - __half2float(h2));
    __half l3 = __float2half(v.w - __half2float(h3));
    *(__half2*)(g_ahi + i)     = __halves2half2(h0, h1);
    *(__half2*)(g_ahi + i + 2) = __halves2half2(h2, h3);
    *(__half2*)(g_alo + i)     = __halves2half2(l0, l1);
    *(__half2*)(g_alo + i + 2) = __halves2half2(l2, l3);
}

// ---------------------------------------------------------------------------
// Kernel B: transpose W fp32 [K,N] -> Wt fp16 [N,K]
// ---------------------------------------------------------------------------
__global__ __launch_bounds__(256) void wtrans_kernel(
    const float* __restrict__ Wq, const float* __restrict__ Wk,
    const float* __restrict__ Wv)
{
    __shared__ float t[32][33];
    const int z = blockIdx.z;
    const float* W = (z == 0) ? Wq : ((z == 1) ? Wk : Wv);
    __half* wt = g_wt + (size_t)z * ND * ND;
    const int n0 = blockIdx.x * 32, k0 = blockIdx.y * 32;
    const int tx = threadIdx.x, ty = threadIdx.y;   // (32, 8)
    #pragma unroll
    for (int i = 0; i < 32; i += 8)
        t[ty + i][tx] = W[(size_t)(k0 + ty + i) * ND + n0 + tx];
    __syncthreads();
    #pragma unroll
    for (int i = 0; i < 32; i += 8)
        wt[(size_t)(n0 + ty + i) * ND + k0 + tx] = __float2half(t[tx][ty + i]);
}

// ---------------------------------------------------------------------------
// Kernel C: QKV projection HMMA fp16 (A split hi+lo, W single), fp32 accum.
// CTA tile 128(m) x 128(n) = 2 heads. BK=32, 24 chunks, 3-stage pipeline.
// 8 warps 4x2 (warp tile 32x64). Grid (65, 6, 3). fp16 output, Q pre-scaled.
// ---------------------------------------------------------------------------
constexpr int QLD   = 40;                     // smem stride, halfs (80 B)
constexpr int QA_SZ = 128 * QLD * 2;          // 10240 B per matrix (128 x 32)
constexpr int QSTG  = 3 * QA_SZ;              // Ahi + Alo + W : 30720 B
constexpr int QS_AHI = 0;
constexpr int QS_ALO = QA_SZ;
constexpr int QS_B   = 2 * QA_SZ;
constexpr int QSM_TOT = 3 * QSTG;             // 92160 B
constexpr int NCH = ND / 32;                  // 24

__global__ __launch_bounds__(256, 2) void qkv_hmma_kernel(
    const float* __restrict__ bq, const float* __restrict__ bk,
    const float* __restrict__ bv)
{
    extern __shared__ char smem[];
    const uint32_t smem_base = smem_to_u32(smem);
    const int tid = threadIdx.x, wid = tid >> 5, lane = tid & 31;
    const int z  = blockIdx.z;
    const int m0 = blockIdx.x * 128;
    const int n0 = blockIdx.y * 128;          // covers heads n0/64, n0/64+1
    const int h0 = n0 >> 6;
    const float* bias = (z == 0) ? bq : ((z == 1) ? bk : bv);
    __half* outb      = (z == 0) ? g_qh : ((z == 1) ? g_kh : g_vh);
    const float oscale = (z == 0) ? 0.125f : 1.0f;
    const __half* Wt = g_wt + (size_t)z * ND * ND;

    const int wm = wid >> 1;                  // 0..3
    const int wn = wid & 1;                   // 0..1 -> 64-col slab
    const int mi = lane >> 3, lr = lane & 7;
    const int ld_row = (mi & 1) * 8 + lr;
    const int ld_col = (mi >> 1) * 8;

    // stage loader: chunk ch -> stage ch%3
    auto load_stage = [&](int ch) {
        const uint32_t sb = smem_base + (ch % 3) * QSTG;
        const int k0 = ch * 32;
        #pragma unroll
        for (int it = 0; it < 2; it++) {
            int lin = it * 256 + tid;
            int row = lin >> 2, c8 = (lin & 3) * 8;
            int m = m0 + row;
            int sz = (m < NM) ? 16 : 0;
            int mc = (m < NM) ? m : (NM - 1);
            uint32_t so = (uint32_t)((row * QLD + c8) * 2);
            cp_async16(sb + QS_AHI + so, g_ahi + (size_t)mc * ND + k0 + c8, sz);
            cp_async16(sb + QS_ALO + so, g_alo + (size_t)mc * ND + k0 + c8, sz);
            cp_async16(sb + QS_B + so,
                       Wt + (size_t)(n0 + row) * ND + k0 + c8, 16);
        }
        CP_COMMIT();
    };

    load_stage(0);
    load_stage(1);

    float acc[2][8][4] = {};

    for (int ch = 0; ch < NCH; ch++) {
        const uint32_t sb = smem_base + (ch % 3) * QSTG;
        if (ch + 2 < NCH) { load_stage(ch + 2); CP_WAIT(2); }
        else if (ch + 1 < NCH) { CP_WAIT(1); }
        else { CP_WAIT(0); }
        __syncthreads();

        #pragma unroll
        for (int k16 = 0; k16 < 2; k16++) {
            const int kc = k16 * 16 + ld_col;
            uint32_t ah[2][4], al[2][4];
            #pragma unroll
            for (int mf = 0; mf < 2; mf++) {
                uint32_t off =
                    (uint32_t)(((wm * 32 + mf * 16 + ld_row) * QLD + kc) * 2);
                ldsm_x4(ah[mf][0], ah[mf][1], ah[mf][2], ah[mf][3],
                        sb + QS_AHI + off);
                ldsm_x4(al[mf][0], al[mf][1], al[mf][2], al[mf][3],
                        sb + QS_ALO + off);
            }
            uint32_t bf[8][2];
            #pragma unroll
            for (int nf2 = 0; nf2 < 4; nf2++) {
                uint32_t off =
                    (uint32_t)(((wn * 64 + nf2 * 16 + ld_row) * QLD + kc) * 2);
                uint32_t t0, t1, t2, t3;
                ldsm_x4(t0, t1, t2, t3, sb + QS_B + off);
                bf[nf2 * 2 + 0][0] = t0; bf[nf2 * 2 + 0][1] = t2;
                bf[nf2 * 2 + 1][0] = t1; bf[nf2 * 2 + 1][1] = t3;
            }
            #pragma unroll
            for (int mf = 0; mf < 2; mf++)
                #pragma unroll
                for (int nf = 0; nf < 8; nf++) {
                    float* c = acc[mf][nf];
                    mma_16816_f16(c[0], c[1], c[2], c[3],
                                  ah[mf][0], ah[mf][1], ah[mf][2], ah[mf][3],
                                  bf[nf][0], bf[nf][1]);
                    mma_16816_f16(c[0], c[1], c[2], c[3],
                                  al[mf][0], al[mf][1], al[mf][2], al[mf][3],
                                  bf[nf][0], bf[nf][1]);
                }
        }
        __syncthreads();
    }

    const int er = lane >> 2, ec = (lane & 3) * 2;
    #pragma unroll
    for (int mf = 0; mf < 2; mf++) {
        #pragma unroll
        for (int half_ = 0; half_ < 2; half_++) {
            const int m = m0 + wm * 32 + mf * 16 + er + half_ * 8;
            if (m >= NM) continue;
            const int bb = m / NS, ss = m - bb * NS;
            #pragma unroll
            for (int nf = 0; nf < 8; nf++) {
                const int c = wn * 64 + nf * 8 + ec;
                const int hh = h0 + (c >> 6);
                __half* op = outb
                    + (((size_t)bb * NH + hh) * NS + ss) * NHD + (c & 63);
                float ox = (acc[mf][nf][half_ * 2 + 0] + bias[n0 + c + 0]) * oscale;
                float oy = (acc[mf][nf][half_ * 2 + 1] + bias[n0 + c + 1]) * oscale;
                *(uint32_t*)op = pack_h2(ox, oy);
            }
        }
    }
}

// ---------------------------------------------------------------------------
// Kernel D: flash attention on HMMA fp16. BQ=128 per CTA, 8 warps x 16 rows,
// BK=64, 2-stage cp.async K/V pipeline. Grid (9, 12, 8).
// Main loop (tiles 0..15) unmasked; tail tile (16) masked.
// ---------------------------------------------------------------------------
constexpr int ALD = 72;                        // fp16 row stride
constexpr int STG = 64 * ALD * 2;              // one K or V stage: 9216 B
constexpr int SMA_Q = 0;                       // 128 x ALD = 18432 B
constexpr int SMA_K = SMA_Q + 128 * ALD * 2;   // 2 stages
constexpr int SMA_V = SMA_K + 2 * STG;         // 2 stages
constexpr int SMA_TOT = SMA_V + 2 * STG;       // 55296 B

__global__ __launch_bounds__(256, 2) void attn_hmma_kernel(
    const float* __restrict__ bias, float* __restrict__ out)
{
    extern __shared__ char smem[];
    const uint32_t smem_base = smem_to_u32(smem);
    const int tid = threadIdx.x, wid = tid >> 5, lane = tid & 31;
    const int q0 = blockIdx.x * 128;
    const int h  = blockIdx.y;
    const int b  = blockIdx.z;

    const __half* Qg = g_qh + ((size_t)(b * NH + h)) * NS * NHD;
    const __half* Kg = g_kh + ((size_t)(b * NH + h)) * NS * NHD;
    const __half* Vg = g_vh + ((size_t)(b * NH + h)) * NS * NHD;
    const float*  Bg = bias + (size_t)h * NS * NS;

    const int mi = lane >> 3, lr = lane & 7;
    const int ld_row = (mi & 1) * 8 + lr;
    const int ld_col = (mi >> 1) * 8;
    const int er = lane >> 2, ec = (lane & 3) * 2;

    const int nkt = (NS + 63) / 64;   // 17 (last tile: 1 valid col)

    auto load_kv = [&](int kt) {
        const int st = kt & 1;
        #pragma unroll
        for (int it = 0; it < 2; it++) {
            int lin = it * 256 + tid;
            int row = lin >> 3, c8 = (lin & 7) * 8;
            int gr = kt * 64 + row;
            int sz = (gr < NS) ? 16 : 0;
            int grc = (gr < NS) ? gr : (NS - 1);
            uint32_t so = (uint32_t)((row * ALD + c8) * 2);
            cp_async16(smem_base + SMA_K + st * STG + so,
                       Kg + (size_t)grc * NHD + c8, sz);
            cp_async16(smem_base + SMA_V + st * STG + so,
                       Vg + (size_t)grc * NHD + c8, sz);
        }
        CP_COMMIT();
    };

    load_kv(0);

    #pragma unroll
    for (int it = 0; it < 4; it++) {
        int lin = it * 256 + tid;
        int row = lin >> 3, c8 = (lin & 7) * 8;
        int sz = (q0 + row < NS) ? 16 : 0;
        int qc = (q0 + row < NS) ? (q0 + row) : (NS - 1);
        cp_async16(smem_base + SMA_Q + (uint32_t)((row * ALD + c8) * 2),
                   Qg + (size_t)qc * NHD + c8, sz);
    }
    CP_COMMIT();
    CP_WAIT(0);
    __syncthreads();

    uint32_t qf[4][4];
    #pragma unroll
    for (int kk = 0; kk < 4; kk++) {
        uint32_t off =
            (uint32_t)(((wid * 16 + ld_row) * ALD + kk * 16 + ld_col) * 2);
        ldsm_x4(qf[kk][0], qf[kk][1], qf[kk][2], qf[kk][3],
                smem_base + SMA_Q + off);
    }

    float ctx[8][4] = {};
    float m_r[2] = {-1e30f, -1e30f};
    float l_r[2] = {0.f, 0.f};
    const int qrow0 = q0 + wid * 16 + er;
    const int qrow1 = qrow0 + 8;
    const float* br0 = Bg + (size_t)((qrow0 < NS) ? qrow0 : (NS - 1)) * NS;
    const float* br1 = Bg + (size_t)((qrow1 < NS) ? qrow1 : (NS - 1)) * NS;

    for (int kt = 0; kt < nkt; kt++) {
        const int k0 = kt * 64;
        const int st = kt & 1;
        const bool tail = (kt == nkt - 1);
        __syncthreads();
        if (!tail) {
            load_kv(kt + 1);
            CP_WAIT(1);
        } else {
            CP_WAIT(0);
        }
        __syncthreads();

        // ---- S = Q K^T ----
        float sf[8][4];
        #pragma unroll
        for (int nf = 0; nf < 8; nf++)
            #pragma unroll
            for (int c = 0; c < 4; c++) sf[nf][c] = 0.f;
        #pragma unroll
        for (int kk = 0; kk < 4; kk++) {
            uint32_t bfr[8][2];
            #pragma unroll
            for (int nf2 = 0; nf2 < 4; nf2++) {
                uint32_t off = (uint32_t)(
                    ((nf2 * 16 + ld_row) * ALD + kk * 16 + ld_col) * 2);
                uint32_t t0, t1, t2, t3;
                ldsm_x4(t0, t1, t2, t3, smem_base + SMA_K + st * STG + off);
                bfr[nf2 * 2 + 0][0] = t0; bfr[nf2 * 2 + 0][1] = t2;
                bfr[nf2 * 2 + 1][0] = t1; bfr[nf2 * 2 + 1][1] = t3;
            }
            #pragma unroll
            for (int nf = 0; nf < 8; nf++)
                mma_16816_f16(sf[nf][0], sf[nf][1], sf[nf][2], sf[nf][3],
                              qf[kk][0], qf[kk][1], qf[kk][2], qf[kk][3],
                              bfr[nf][0], bfr[nf][1]);
        }

        // ---- bias + (tail-only mask) + online softmax, in registers ----
        #pragma unroll
        for (int r = 0; r < 2; r++) {
            const float* br = r ? br1 : br0;
            float mx = m_r[r];
            if (!tail) {
                #pragma unroll
                for (int nf = 0; nf < 8; nf++) {
                    #pragma unroll
                    for (int c = 0; c < 2; c++) {
                        float s = sf[nf][r * 2 + c]
                                + __ldg(br + k0 + nf * 8 + ec + c);
                        sf[nf][r * 2 + c] = s;
                        mx = fmaxf(mx, s);
                    }
                }
            } else {
                #pragma unroll
                for (int nf = 0; nf < 8; nf++) {
                    #pragma unroll
                    for (int c = 0; c < 2; c++) {
                        const int kcol = k0 + nf * 8 + ec + c;
                        float s = (kcol < NS)
                            ? (sf[nf][r * 2 + c] + __ldg(br + kcol))
                            : -1e30f;
                        sf[nf][r * 2 + c] = s;
                        mx = fmaxf(mx, s);
                    }
                }
            }
            mx = fmaxf(mx, __shfl_xor_sync(0xffffffffu, mx, 1));
            mx = fmaxf(mx, __shfl_xor_sync(0xffffffffu, mx, 2));
            const float scale_f = __expf(m_r[r] - mx);
            float l = l_r[r] * scale_f;
            #pragma unroll
            for (int nf = 0; nf < 8; nf++) {
                #pragma unroll
                for (int c = 0; c < 2; c++) {
                    float p = __expf(sf[nf][r * 2 + c] - mx);
                    sf[nf][r * 2 + c] = p;
                    l += p;
                }
            }
            m_r[r] = mx;
            l_r[r] = l;
            #pragma unroll
            for (int df = 0; df < 8; df++) {
                ctx[df][r * 2 + 0] *= scale_f;
                ctx[df][r * 2 + 1] *= scale_f;
            }
        }

        // ---- pack P into A frags (register-direct) ----
        uint32_t pa[4][4];
        #pragma unroll
        for (int kk = 0; kk < 4; kk++) {
            pa[kk][0] = pack_h2(sf[2 * kk + 0][0], sf[2 * kk + 0][1]);
            pa[kk][1] = pack_h2(sf[2 * kk + 0][2], sf[2 * kk + 0][3]);
            pa[kk][2] = pack_h2(sf[2 * kk + 1][0], sf[2 * kk + 1][1]);
            pa[kk][3] = pack_h2(sf[2 * kk + 1][2], sf[2 * kk + 1][3]);
        }

        // ---- ctx += P V ----
        const int g = lane >> 3;
        #pragma unroll
        for (int kk = 0; kk < 4; kk++) {
            uint32_t vb[8][2];
            #pragma unroll
            for (int df2 = 0; df2 < 4; df2++) {
                uint32_t off = (uint32_t)(
                    ((kk * 16 + (g & 1) * 8 + (lane & 7)) * ALD
                     + df2 * 16 + (g >> 1) * 8) * 2);
                uint32_t t0, t1, t2, t3;
                ldsm_x4_trans(t0, t1, t2, t3,
                              smem_base + SMA_V + st * STG + off);
                vb[df2 * 2 + 0][0] = t0; vb[df2 * 2 + 0][1] = t1;
                vb[df2 * 2 + 1][0] = t2; vb[df2 * 2 + 1][1] = t3;
            }
            #pragma unroll
            for (int df = 0; df < 8; df++)
                mma_16816_f16(ctx[df][0], ctx[df][1], ctx[df][2], ctx[df][3],
                              pa[kk][0], pa[kk][1], pa[kk][2], pa[kk][3],
                              vb[df][0], vb[df][1]);
        }
    }

    // ---- epilogue ----
    #pragma unroll
    for (int r = 0; r < 2; r++) {
        float l = l_r[r];
        l += __shfl_xor_sync(0xffffffffu, l, 1);
        l += __shfl_xor_sync(0xffffffffu, l, 2);
        l_r[r] = l;
    }
    #pragma unroll
    for (int r = 0; r < 2; r++) {
        const int q = r ? qrow1 : qrow0;
        if (q >= NS) continue;
        const float inv = 1.0f / l_r[r];
        float* op = out + ((size_t)b * NS + q) * ND + h * NHD;
        #pragma unroll
        for (int df = 0; df < 8; df++) {
            float2 o;
            o.x = ctx[df][r * 2 + 0] * inv;
            o.y = ctx[df][r * 2 + 1] * inv;
            *(float2*)(op + df * 8 + ec) = o;
        }
    }
}

// ---------------------------------------------------------------------------
extern "C" void kernel_launch(void* const* d_in, const int* in_sizes, int n_in,
                              void* d_out, int out_size)
{
    const float* hs = (const float*)d_in[0];
    const float* rb = (const float*)d_in[1];
    const float* Wq = (const float*)d_in[2];
    const float* bq = (const float*)d_in[3];
    const float* Wk = (const float*)d_in[4];
    const float* bk = (const float*)d_in[5];
    const float* Wv = (const float*)d_in[6];
    const float* bv = (const float*)d_in[7];
    float* out = (float*)d_out;

    aconv_kernel<<<(int)(((size_t)NM * ND / 4 + 255) / 256), 256>>>(hs);
    dim3 gw(ND / 32, ND / 32, 3);
    wtrans_kernel<<<gw, dim3(32, 8)>>>(Wq, Wk, Wv);

    cudaFuncSetAttribute(qkv_hmma_kernel,
                         cudaFuncAttributeMaxDynamicSharedMemorySize, QSM_TOT);
    dim3 g1((NM + 127) / 128, ND / 128, 3);
    qkv_hmma_kernel<<<g1, 256, QSM_TOT>>>(bq, bk, bv);

    cudaFuncSetAttribute(attn_hmma_kernel,
                         cudaFuncAttributeMaxDynamicSharedMemorySize, SMA_TOT);
    dim3 g2((NS + 127) / 128, NH, NB);
    attn_hmma_kernel<<<g2, 256, SMA_TOT>>>(rb, out);
}

// round 15
// speedup vs baseline: 1.3482x; 1.3482x over previous
#include <cuda_runtime.h>
#include <cuda_bf16.h>
#include <cuda_fp16.h>
#include <cstdint>

// Problem constants
constexpr int NB  = 8;
constexpr int NS  = 1025;
constexpr int ND  = 768;
constexpr int NH  = 12;
constexpr int NHD = 64;
constexpr int NM  = NB * NS;      // 8200
constexpr float LOG2E = 1.4426950408889634f;

// Padded bias dims
constexpr int BQR = 1152;         // 9 * 128
constexpr int BKC = 1088;         // 17 * 64

// Scratch
__device__ __half g_qh[(size_t)NB * NH * NS * NHD];   // q * 0.125 * log2e
__device__ __half g_kh[(size_t)NB * NH * NS * NHD];
__device__ __half g_vh[(size_t)NB * NH * NS * NHD];
__device__ __half g_ahi[(size_t)NM * ND];
__device__ __half g_alo[(size_t)NM * ND];
__device__ __half g_wt[(size_t)3 * ND * ND];          // W^T [n][k], fp16
__device__ float  g_b2[(size_t)NH * BQR * BKC];       // bias * log2e, padded

// ---------------------------------------------------------------------------
// PTX helpers
// ---------------------------------------------------------------------------
__device__ __forceinline__ uint32_t smem_to_u32(const void* p) {
    uint32_t a;
    asm("{ .reg .u64 t; cvta.to.shared.u64 t, %1; cvt.u32.u64 %0, t; }"
        : "=r"(a) : "l"(p));
    return a;
}
__device__ __forceinline__ void ldsm_x4(uint32_t& r0, uint32_t& r1,
                                        uint32_t& r2, uint32_t& r3,
                                        uint32_t addr) {
    asm volatile("ldmatrix.sync.aligned.m8n8.x4.shared.b16 {%0,%1,%2,%3}, [%4];"
                 : "=r"(r0), "=r"(r1), "=r"(r2), "=r"(r3) : "r"(addr));
}
__device__ __forceinline__ void ldsm_x4_trans(uint32_t& r0, uint32_t& r1,
                                              uint32_t& r2, uint32_t& r3,
                                              uint32_t addr) {
    asm volatile("ldmatrix.sync.aligned.m8n8.x4.trans.shared.b16 {%0,%1,%2,%3}, [%4];"
                 : "=r"(r0), "=r"(r1), "=r"(r2), "=r"(r3) : "r"(addr));
}
__device__ __forceinline__ void mma_16816_f16(
    float& c0, float& c1, float& c2, float& c3,
    uint32_t a0, uint32_t a1, uint32_t a2, uint32_t a3,
    uint32_t b0, uint32_t b1) {
    asm volatile(
        "mma.sync.aligned.m16n8k16.row.col.f32.f16.f16.f32 "
        "{%0,%1,%2,%3}, {%4,%5,%6,%7}, {%8,%9}, {%0,%1,%2,%3};"
        : "+f"(c0), "+f"(c1), "+f"(c2), "+f"(c3)
        : "r"(a0), "r"(a1), "r"(a2), "r"(a3), "r"(b0), "r"(b1));
}
__device__ __forceinline__ uint32_t pack_h2(float lo, float hi) {
    uint32_t r;
    asm("cvt.rn.f16x2.f32 %0, %1, %2;" : "=r"(r) : "f"(hi), "f"(lo));
    return r;
}
__device__ __forceinline__ uint32_t h2_sub(uint32_t a, uint32_t b) {
    uint32_t r;
    asm("sub.f16x2 %0, %1, %2;" : "=r"(r) : "r"(a), "r"(b));
    return r;
}
__device__ __forceinline__ uint32_t h2_ex2(uint32_t x) {
    uint32_t r;
    asm("ex2.approx.f16x2 %0, %1;" : "=r"(r) : "r"(x));
    return r;
}
__device__ __forceinline__ void cp_async16(uint32_t dst, const void* src,
                                           int szbytes) {
    asm volatile("cp.async.cg.shared.global [%0], [%1], 16, %2;"
                 :: "r"(dst), "l"(src), "r"(szbytes));
}
#define CP_COMMIT() asm volatile("cp.async.commit_group;" ::: "memory")
#define CP_WAIT(n)  asm volatile("cp.async.wait_group %0;" :: "n"(n) : "memory")

// ---------------------------------------------------------------------------
// Kernel A: split hidden_states fp32 -> (hi, lo) fp16
// ---------------------------------------------------------------------------
__global__ __launch_bounds__(256) void aconv_kernel(const float* __restrict__ A)
{
    size_t i = ((size_t)blockIdx.x * 256 + threadIdx.x) * 4;
    if (i >= (size_t)NM * ND) return;
    float4 v = *(const float4*)(A + i);
    __half h0 = __float2half(v.x), h1 = __float2half(v.y);
    __half h2 = __float2half(v.z), h3 = __float2half(v.w);
    __half l0 = __float2half(v.x - __half2float(h0));
    __half l1 = __float2half(v.y - __half2float(h1));
    __half l2 = __float2half(v.z - __half2float(h2));
    __half l3 = __float2half(v.w - __half2float(h3));
    *(__half2*)(g_ahi + i)     = __halves2half2(h0, h1);
    *(__half2*)(g_ahi + i + 2) = __halves2half2(h2, h3);
    *(__half2*)(g_alo + i)     = __halves2half2(l0, l1);
    *(__half2*)(g_alo + i + 2) = __halves2half2(l2, l3);
}

// ---------------------------------------------------------------------------
// Kernel B: transpose W fp32 [K,N] -> Wt fp16 [N,K]
// ---------------------------------------------------------------------------
__global__ __launch_bounds__(256) void wtrans_kernel(
    const float* __restrict__ Wq, const float* __restrict__ Wk,
    const float* __restrict__ Wv)
{
    __shared__ float t[32][33];
    const int z = blockIdx.z;
    const float* W = (z == 0) ? Wq : ((z == 1) ? Wk : Wv);
    __half* wt = g_wt + (size_t)z * ND * ND;
    const int n0 = blockIdx.x * 32, k0 = blockIdx.y * 32;
    const int tx = threadIdx.x, ty = threadIdx.y;   // (32, 8)
    #pragma unroll
    for (int i = 0; i < 32; i += 8)
        t[ty + i][tx] = W[(size_t)(k0 + ty + i) * ND + n0 + tx];
    __syncthreads();
    #pragma unroll
    for (int i = 0; i < 32; i += 8)
        wt[(size_t)(n0 + ty + i) * ND + k0 + tx] = __float2half(t[tx][ty + i]);
}

// ---------------------------------------------------------------------------
// Kernel B2: pad rel_bias into [NH][BQR][BKC], * log2e, OOB = -1e30
// ---------------------------------------------------------------------------
__global__ __launch_bounds__(256) void bias_pad_kernel(const float* __restrict__ rb)
{
    size_t i = (size_t)blockIdx.x * 256 + threadIdx.x;   // one float4
    if (i >= (size_t)NH * BQR * (BKC / 4)) return;
    int k4 = (int)(i % (BKC / 4)) * 4;
    size_t t = i / (BKC / 4);
    int q = (int)(t % BQR);
    int h = (int)(t / BQR);
    float4 o = make_float4(-1e30f, -1e30f, -1e30f, -1e30f);
    if (q < NS) {
        const float* src = rb + ((size_t)h * NS + q) * NS;
        if (k4 + 0 < NS) o.x = src[k4 + 0] * LOG2E;
        if (k4 + 1 < NS) o.y = src[k4 + 1] * LOG2E;
        if (k4 + 2 < NS) o.z = src[k4 + 2] * LOG2E;
        if (k4 + 3 < NS) o.w = src[k4 + 3] * LOG2E;
    }
    *(float4*)(g_b2 + ((size_t)h * BQR + q) * BKC + k4) = o;
}

// ---------------------------------------------------------------------------
// Kernel C: QKV projection HMMA fp16 (A split hi+lo, W single), fp32 accum.
// CTA tile 128x64, BK=32, 24 chunks, 3-stage cp.async pipeline. (round-9)
// ---------------------------------------------------------------------------
constexpr int QLD   = 40;
constexpr int QA_SZ = 128 * QLD * 2;          // 10240 B
constexpr int QB_SZ = 64 * QLD * 2;           // 5120 B
constexpr int QSTG  = 2 * QA_SZ + QB_SZ;      // 25600 B
constexpr int QS_AHI = 0;
constexpr int QS_ALO = QA_SZ;
constexpr int QS_B   = 2 * QA_SZ;
constexpr int QSM_TOT = 3 * QSTG;             // 76800 B
constexpr int NCH = ND / 32;                  // 24

__global__ __launch_bounds__(256, 2) void qkv_hmma_kernel(
    const float* __restrict__ bq, const float* __restrict__ bk,
    const float* __restrict__ bv)
{
    extern __shared__ char smem[];
    const uint32_t smem_base = smem_to_u32(smem);
    const int tid = threadIdx.x, wid = tid >> 5, lane = tid & 31;
    const int z  = blockIdx.z;
    const int m0 = blockIdx.x * 128;
    const int h  = blockIdx.y;
    const int n0 = h * 64;
    const float* bias = (z == 0) ? bq : ((z == 1) ? bk : bv);
    __half* outb      = (z == 0) ? g_qh : ((z == 1) ? g_kh : g_vh);
    const float oscale = (z == 0) ? (0.125f * LOG2E) : 1.0f;
    const __half* Wt = g_wt + (size_t)z * ND * ND;

    const int wm = wid >> 1;
    const int wn = wid & 1;
    const int mi = lane >> 3, lr = lane & 7;
    const int ld_row = (mi & 1) * 8 + lr;
    const int ld_col = (mi >> 1) * 8;

    auto load_stage = [&](int ch) {
        const uint32_t sb = smem_base + (ch % 3) * QSTG;
        const int k0 = ch * 32;
        #pragma unroll
        for (int it = 0; it < 2; it++) {
            int lin = it * 256 + tid;
            int row = lin >> 2, c8 = (lin & 3) * 8;
            int m = m0 + row;
            int sz = (m < NM) ? 16 : 0;
            int mc = (m < NM) ? m : (NM - 1);
            uint32_t so = (uint32_t)((row * QLD + c8) * 2);
            cp_async16(sb + QS_AHI + so, g_ahi + (size_t)mc * ND + k0 + c8, sz);
            cp_async16(sb + QS_ALO + so, g_alo + (size_t)mc * ND + k0 + c8, sz);
        }
        {
            int row = tid >> 2, c8 = (tid & 3) * 8;
            uint32_t so = (uint32_t)((row * QLD + c8) * 2);
            cp_async16(sb + QS_B + so, Wt + (size_t)(n0 + row) * ND + k0 + c8, 16);
        }
        CP_COMMIT();
    };

    load_stage(0);
    load_stage(1);

    float acc[2][4][4] = {};

    for (int ch = 0; ch < NCH; ch++) {
        const uint32_t sb = smem_base + (ch % 3) * QSTG;
        if (ch + 2 < NCH) { load_stage(ch + 2); CP_WAIT(2); }
        else if (ch + 1 < NCH) { CP_WAIT(1); }
        else { CP_WAIT(0); }
        __syncthreads();

        #pragma unroll
        for (int k16 = 0; k16 < 2; k16++) {
            const int kc = k16 * 16 + ld_col;
            uint32_t ah[2][4], al[2][4];
            #pragma unroll
            for (int mf = 0; mf < 2; mf++) {
                uint32_t off =
                    (uint32_t)(((wm * 32 + mf * 16 + ld_row) * QLD + kc) * 2);
                ldsm_x4(ah[mf][0], ah[mf][1], ah[mf][2], ah[mf][3],
                        sb + QS_AHI + off);
                ldsm_x4(al[mf][0], al[mf][1], al[mf][2], al[mf][3],
                        sb + QS_ALO + off);
            }
            uint32_t bf[4][2];
            #pragma unroll
            for (int nf2 = 0; nf2 < 2; nf2++) {
                uint32_t off =
                    (uint32_t)(((wn * 32 + nf2 * 16 + ld_row) * QLD + kc) * 2);
                uint32_t t0, t1, t2, t3;
                ldsm_x4(t0, t1, t2, t3, sb + QS_B + off);
                bf[nf2 * 2 + 0][0] = t0; bf[nf2 * 2 + 0][1] = t2;
                bf[nf2 * 2 + 1][0] = t1; bf[nf2 * 2 + 1][1] = t3;
            }
            #pragma unroll
            for (int mf = 0; mf < 2; mf++)
                #pragma unroll
                for (int nf = 0; nf < 4; nf++) {
                    float* c = acc[mf][nf];
                    mma_16816_f16(c[0], c[1], c[2], c[3],
                                  ah[mf][0], ah[mf][1], ah[mf][2], ah[mf][3],
                                  bf[nf][0], bf[nf][1]);
                    mma_16816_f16(c[0], c[1], c[2], c[3],
                                  al[mf][0], al[mf][1], al[mf][2], al[mf][3],
                                  bf[nf][0], bf[nf][1]);
                }
        }
        __syncthreads();
    }

    const int er = lane >> 2, ec = (lane & 3) * 2;
    #pragma unroll
    for (int mf = 0; mf < 2; mf++) {
        #pragma unroll
        for (int half_ = 0; half_ < 2; half_++) {
            const int m = m0 + wm * 32 + mf * 16 + er + half_ * 8;
            if (m >= NM) continue;
            const int bb = m / NS, ss = m - bb * NS;
            __half* op = outb + (((size_t)bb * NH + h) * NS + ss) * NHD;
            #pragma unroll
            for (int nf = 0; nf < 4; nf++) {
                const int c = wn * 32 + nf * 8 + ec;
                float ox = (acc[mf][nf][half_ * 2 + 0] + bias[n0 + c + 0]) * oscale;
                float oy = (acc[mf][nf][half_ * 2 + 1] + bias[n0 + c + 1]) * oscale;
                *(uint32_t*)(op + c) = pack_h2(ox, oy);
            }
        }
    }
}

// ---------------------------------------------------------------------------
// Kernel D: flash attention, HMMA fp16, log2-domain softmax via ex2.f16x2,
// l via ones-MMA. BQ=128, BK=64, 2-stage cp.async. Uniform 17-tile loop.
// ---------------------------------------------------------------------------
constexpr int ALD = 72;
constexpr int STG = 64 * ALD * 2;
constexpr int SMA_Q = 0;
constexpr int SMA_K = SMA_Q + 128 * ALD * 2;
constexpr int SMA_V = SMA_K + 2 * STG;
constexpr int SMA_TOT = SMA_V + 2 * STG;       // 55296 B

__global__ __launch_bounds__(256, 2) void attn_hmma_kernel(float* __restrict__ out)
{
    extern __shared__ char smem[];
    const uint32_t smem_base = smem_to_u32(smem);
    const int tid = threadIdx.x, wid = tid >> 5, lane = tid & 31;
    const int q0 = blockIdx.x * 128;
    const int h  = blockIdx.y;
    const int b  = blockIdx.z;

    const __half* Qg = g_qh + ((size_t)(b * NH + h)) * NS * NHD;
    const __half* Kg = g_kh + ((size_t)(b * NH + h)) * NS * NHD;
    const __half* Vg = g_vh + ((size_t)(b * NH + h)) * NS * NHD;

    const int mi = lane >> 3, lr = lane & 7;
    const int ld_row = (mi & 1) * 8 + lr;
    const int ld_col = (mi >> 1) * 8;
    const int er = lane >> 2, ec = (lane & 3) * 2;

    const int nkt = BKC / 64;   // 17, uniform (K zero-filled, bias -1e30)
    const uint32_t ONES = 0x3C003C00u;   // half2(1,1)

    auto load_kv = [&](int kt) {
        const int st = kt & 1;
        #pragma unroll
        for (int it = 0; it < 2; it++) {
            int lin = it * 256 + tid;
            int row = lin >> 3, c8 = (lin & 7) * 8;
            int gr = kt * 64 + row;
            int sz = (gr < NS) ? 16 : 0;
            int grc = (gr < NS) ? gr : (NS - 1);
            uint32_t so = (uint32_t)((row * ALD + c8) * 2);
            cp_async16(smem_base + SMA_K + st * STG + so,
                       Kg + (size_t)grc * NHD + c8, sz);
            cp_async16(smem_base + SMA_V + st * STG + so,
                       Vg + (size_t)grc * NHD + c8, sz);
        }
        CP_COMMIT();
    };

    load_kv(0);

    #pragma unroll
    for (int it = 0; it < 4; it++) {
        int lin = it * 256 + tid;
        int row = lin >> 3, c8 = (lin & 7) * 8;
        int sz = (q0 + row < NS) ? 16 : 0;
        int qc = (q0 + row < NS) ? (q0 + row) : (NS - 1);
        cp_async16(smem_base + SMA_Q + (uint32_t)((row * ALD + c8) * 2),
                   Qg + (size_t)qc * NHD + c8, sz);
    }
    CP_COMMIT();
    CP_WAIT(0);
    __syncthreads();

    uint32_t qf[4][4];
    #pragma unroll
    for (int kk = 0; kk < 4; kk++) {
        uint32_t off =
            (uint32_t)(((wid * 16 + ld_row) * ALD + kk * 16 + ld_col) * 2);
        ldsm_x4(qf[kk][0], qf[kk][1], qf[kk][2], qf[kk][3],
                smem_base + SMA_Q + off);
    }

    float ctx[8][4] = {};
    float lacc[4] = {};
    float m_r[2] = {-1e30f, -1e30f};
    const int qrow0 = q0 + wid * 16 + er;       // < BQR always
    const int qrow1 = qrow0 + 8;
    const float* br0 = g_b2 + ((size_t)h * BQR + qrow0) * BKC;
    const float* br1 = g_b2 + ((size_t)h * BQR + qrow1) * BKC;

    for (int kt = 0; kt < nkt; kt++) {
        const int k0 = kt * 64;
        const int st = kt & 1;
        __syncthreads();
        if (kt + 1 < nkt) { load_kv(kt + 1); CP_WAIT(1); }
        else { CP_WAIT(0); }
        __syncthreads();

        // ---- S = Q K^T (log2-domain: Q pre-scaled by 0.125*log2e) ----
        float sf[8][4];
        #pragma unroll
        for (int nf = 0; nf < 8; nf++)
            #pragma unroll
            for (int c = 0; c < 4; c++) sf[nf][c] = 0.f;
        #pragma unroll
        for (int kk = 0; kk < 4; kk++) {
            uint32_t bfr[8][2];
            #pragma unroll
            for (int nf2 = 0; nf2 < 4; nf2++) {
                uint32_t off = (uint32_t)(
                    ((nf2 * 16 + ld_row) * ALD + kk * 16 + ld_col) * 2);
                uint32_t t0, t1, t2, t3;
                ldsm_x4(t0, t1, t2, t3, smem_base + SMA_K + st * STG + off);
                bfr[nf2 * 2 + 0][0] = t0; bfr[nf2 * 2 + 0][1] = t2;
                bfr[nf2 * 2 + 1][0] = t1; bfr[nf2 * 2 + 1][1] = t3;
            }
            #pragma unroll
            for (int nf = 0; nf < 8; nf++)
                mma_16816_f16(sf[nf][0], sf[nf][1], sf[nf][2], sf[nf][3],
                              qf[kk][0], qf[kk][1], qf[kk][2], qf[kk][3],
                              bfr[nf][0], bfr[nf][1]);
        }

        // ---- bias (padded, no masks) + max ----
        float mx0 = m_r[0], mx1 = m_r[1];
        #pragma unroll
        for (int nf = 0; nf < 8; nf++) {
            float2 b0 = *(const float2*)(br0 + k0 + nf * 8 + ec);
            sf[nf][0] += b0.x; sf[nf][1] += b0.y;
            mx0 = fmaxf(mx0, fmaxf(sf[nf][0], sf[nf][1]));
            float2 b1 = *(const float2*)(br1 + k0 + nf * 8 + ec);
            sf[nf][2] += b1.x; sf[nf][3] += b1.y;
            mx1 = fmaxf(mx1, fmaxf(sf[nf][2], sf[nf][3]));
        }
        mx0 = fmaxf(mx0, __shfl_xor_sync(0xffffffffu, mx0, 1));
        mx0 = fmaxf(mx0, __shfl_xor_sync(0xffffffffu, mx0, 2));
        mx1 = fmaxf(mx1, __shfl_xor_sync(0xffffffffu, mx1, 1));
        mx1 = fmaxf(mx1, __shfl_xor_sync(0xffffffffu, mx1, 2));
        const float sc0 = exp2f(m_r[0] - mx0);
        const float sc1 = exp2f(m_r[1] - mx1);
        m_r[0] = mx0; m_r[1] = mx1;
        const uint32_t mxh0 = pack_h2(mx0, mx0);
        const uint32_t mxh1 = pack_h2(mx1, mx1);

        // ---- P = ex2(s - m) in fp16x2, directly as A-fragments ----
        uint32_t pa[4][4];
        #pragma unroll
        for (int kk = 0; kk < 4; kk++) {
            pa[kk][0] = h2_ex2(h2_sub(pack_h2(sf[2*kk+0][0], sf[2*kk+0][1]), mxh0));
            pa[kk][1] = h2_ex2(h2_sub(pack_h2(sf[2*kk+0][2], sf[2*kk+0][3]), mxh1));
            pa[kk][2] = h2_ex2(h2_sub(pack_h2(sf[2*kk+1][0], sf[2*kk+1][1]), mxh0));
            pa[kk][3] = h2_ex2(h2_sub(pack_h2(sf[2*kk+1][2], sf[2*kk+1][3]), mxh1));
        }

        // ---- rescale accumulators ----
        #pragma unroll
        for (int df = 0; df < 8; df++) {
            ctx[df][0] *= sc0; ctx[df][1] *= sc0;
            ctx[df][2] *= sc1; ctx[df][3] *= sc1;
        }
        lacc[0] *= sc0; lacc[1] *= sc0;
        lacc[2] *= sc1; lacc[3] *= sc1;

        // ---- l += P @ ones (tensor pipe) ----
        #pragma unroll
        for (int kk = 0; kk < 4; kk++)
            mma_16816_f16(lacc[0], lacc[1], lacc[2], lacc[3],
                          pa[kk][0], pa[kk][1], pa[kk][2], pa[kk][3],
                          ONES, ONES);

        // ---- ctx += P V ----
        const int g = lane >> 3;
        #pragma unroll
        for (int kk = 0; kk < 4; kk++) {
            uint32_t vb[8][2];
            #pragma unroll
            for (int df2 = 0; df2 < 4; df2++) {
                uint32_t off = (uint32_t)(
                    ((kk * 16 + (g & 1) * 8 + (lane & 7)) * ALD
                     + df2 * 16 + (g >> 1) * 8) * 2);
                uint32_t t0, t1, t2, t3;
                ldsm_x4_trans(t0, t1, t2, t3,
                              smem_base + SMA_V + st * STG + off);
                vb[df2 * 2 + 0][0] = t0; vb[df2 * 2 + 0][1] = t1;
                vb[df2 * 2 + 1][0] = t2; vb[df2 * 2 + 1][1] = t3;
            }
            #pragma unroll
            for (int df = 0; df < 8; df++)
                mma_16816_f16(ctx[df][0], ctx[df][1], ctx[df][2], ctx[df][3],
                              pa[kk][0], pa[kk][1], pa[kk][2], pa[kk][3],
                              vb[df][0], vb[df][1]);
        }
    }

    // ---- epilogue: l already k-reduced by the ones-MMA ----
    #pragma unroll
    for (int r = 0; r < 2; r++) {
        const int q = r ? qrow1 : qrow0;
        if (q >= NS) continue;
        const float inv = 1.0f / lacc[r * 2];
        float* op = out + ((size_t)b * NS + q) * ND + h * NHD;
        #pragma unroll
        for (int df = 0; df < 8; df++) {
            float2 o;
            o.x = ctx[df][r * 2 + 0] * inv;
            o.y = ctx[df][r * 2 + 1] * inv;
            *(float2*)(op + df * 8 + ec) = o;
        }
    }
}

// ---------------------------------------------------------------------------
extern "C" void kernel_launch(void* const* d_in, const int* in_sizes, int n_in,
                              void* d_out, int out_size)
{
    const float* hs = (const float*)d_in[0];
    const float* rb = (const float*)d_in[1];
    const float* Wq = (const float*)d_in[2];
    const float* bq = (const float*)d_in[3];
    const float* Wk = (const float*)d_in[4];
    const float* bk = (const float*)d_in[5];
    const float* Wv = (const float*)d_in[6];
    const float* bv = (const float*)d_in[7];
    float* out = (float*)d_out;

    aconv_kernel<<<(int)(((size_t)NM * ND / 4 + 255) / 256), 256>>>(hs);
    dim3 gw(ND / 32, ND / 32, 3);
    wtrans_kernel<<<gw, dim3(32, 8)>>>(Wq, Wk, Wv);
    bias_pad_kernel<<<(int)(((size_t)NH * BQR * (BKC / 4) + 255) / 256), 256>>>(rb);

    cudaFuncSetAttribute(qkv_hmma_kernel,
                         cudaFuncAttributeMaxDynamicSharedMemorySize, QSM_TOT);
    dim3 g1((NM + 127) / 128, NH, 3);
    qkv_hmma_kernel<<<g1, 256, QSM_TOT>>>(bq, bk, bv);

    cudaFuncSetAttribute(attn_hmma_kernel,
                         cudaFuncAttributeMaxDynamicSharedMemorySize, SMA_TOT);
    dim3 g2((NS + 127) / 128, NH, NB);
    attn_hmma_kernel<<<g2, 256, SMA_TOT>>>(out);
}